// round 15
// baseline (speedup 1.0000x reference)
#include <cuda_runtime.h>
#include <cuda_fp16.h>
#include <math.h>
#include <stdint.h>

// ---------------- problem constants ----------------
#define S_LEN 2048
#define HID   3584
#define NH    28
#define NKV   4
#define HD    128
#define NQD   (NH*HD)    // 3584
#define NKD   (NKV*HD)   // 512
#define GRP   (NH/NKV)   // 7
#define NQKV  (NQD + 2*NKD)  // 4608

// ---------------- scratch (device globals; no allocs allowed) ----------------
__device__ float g_bias[NQKV];

__device__ __align__(16) __half g_hs16[S_LEN * HID];
__device__ __align__(16) __half g_ctx16[S_LEN * NQD];
__device__ __align__(16) __half g_q16h[S_LEN * NQD], g_q16l[S_LEN * NQD];
__device__ __align__(16) __half g_k16[S_LEN * NKD];
__device__ __align__(16) __half g_v16[S_LEN * NKD];
__device__ __align__(16) __half g_w16[(size_t)NQKV * HID];
__device__ __align__(16) __half g_wo16[(size_t)HID * NQD];

// ---------------- helpers ----------------
__device__ __forceinline__ uint32_t smem_u32(const void* p) {
    uint32_t a;
    asm("{ .reg .u64 t; cvta.to.shared.u64 t, %1; cvt.u32.u64 %0, t; }" : "=r"(a) : "l"(p));
    return a;
}

__device__ __forceinline__ void cp_async16(uint32_t dst, const void* src) {
    asm volatile("cp.async.cg.shared.global [%0], [%1], 16;" :: "r"(dst), "l"(src) : "memory");
}

__device__ __forceinline__ void ldm_x4(uint32_t* r, uint32_t addr) {
    asm volatile("ldmatrix.sync.aligned.m8n8.x4.shared.b16 {%0,%1,%2,%3}, [%4];"
                 : "=r"(r[0]), "=r"(r[1]), "=r"(r[2]), "=r"(r[3]) : "r"(addr));
}

__device__ __forceinline__ void ldm_x4_t(uint32_t* r, uint32_t addr) {
    asm volatile("ldmatrix.sync.aligned.m8n8.x4.trans.shared.b16 {%0,%1,%2,%3}, [%4];"
                 : "=r"(r[0]), "=r"(r[1]), "=r"(r[2]), "=r"(r[3]) : "r"(addr));
}

__device__ __forceinline__ void mma_f16(float* c, const uint32_t* a, const uint32_t* b) {
    asm volatile(
        "mma.sync.aligned.m16n8k16.row.col.f32.f16.f16.f32 "
        "{%0,%1,%2,%3}, {%4,%5,%6,%7}, {%8,%9}, {%0,%1,%2,%3};"
        : "+f"(c[0]), "+f"(c[1]), "+f"(c[2]), "+f"(c[3])
        : "r"(a[0]), "r"(a[1]), "r"(a[2]), "r"(a[3]), "r"(b[0]), "r"(b[1]));
}

__device__ __forceinline__ uint32_t pack_h2(float a, float b) {
    __half2 h = __floats2half2_rn(a, b);
    return *(uint32_t*)&h;
}

__device__ __forceinline__ float fexp2(float x) {
    float r;
    asm("ex2.approx.f32 %0, %1;" : "=f"(r) : "f"(x));
    return r;
}

// ---------------- convert kernels ----------------
__global__ void conv_h_kernel(const float4* __restrict__ X, __half2* __restrict__ H, int n4) {
    int i = blockIdx.x * 256 + threadIdx.x;
    if (i >= n4) return;
    float4 x = X[i];
    H[2*i]   = __floats2half2_rn(x.x, x.y);
    H[2*i+1] = __floats2half2_rn(x.z, x.w);
}

// W [K,N] fp32 row-major -> T [N,K] fp16 (single). Tile 32n x 64k, block (32,8).
__global__ void tsplit2h_kernel(const float* __restrict__ W, __half* __restrict__ T,
                                int K, int N) {
    __shared__ float t[64][33];
    int n0 = blockIdx.x * 32, k0 = blockIdx.y * 64;
    int tx = threadIdx.x, ty = threadIdx.y;
#pragma unroll
    for (int i = 0; i < 8; i++) {
        int k = i * 8 + ty;
        t[k][tx] = W[(size_t)(k0 + k) * N + n0 + tx];
    }
    __syncthreads();
#pragma unroll
    for (int i = 0; i < 4; i++) {
        int n = i * 8 + ty;
        __half2 hp = __floats2half2_rn(t[2 * tx][n], t[2 * tx + 1][n]);
        *(__half2*)(T + (size_t)(n0 + n) * K + k0 + 2 * tx) = hp;
    }
}

__global__ void concat_bias_kernel(const float* __restrict__ bq, const float* __restrict__ bk,
                                   const float* __restrict__ bv, float* __restrict__ b) {
    int i = blockIdx.x * 256 + threadIdx.x;
    if (i < NQD) b[i] = bq[i];
    else if (i < NQD + NKD) b[i] = bk[i - NQD];
    else if (i < NQKV) b[i] = bv[i - NQD - NKD];
}

// ---------------- GEMM tiling constants ----------------
#define GBK 32
#define ROWP 40
#define STG_TILE (128*ROWP*2)          // 10240 B per operand tile
#define STG1_BYTES (2*STG_TILE)        // 20480 B per stage (A, B)
#define GEMM1_SMEM (3*STG1_BYTES)      // 61440 B (3 stages)
#define EP_STRIDE 132
#define FUSED_SMEM (128*EP_STRIDE*4)   // 67584 B (epilogue staging; > pipeline bytes)

// ---------------- GEMM mainloop (shared) ----------------
struct GemmCore {
    uint32_t sb;
    int tid, lane, warp, wm, wn, row0, col0;
    float acc[4][4][4];

    __device__ __forceinline__ void init(uint32_t sb_, int row0_, int col0_) {
        sb = sb_;
        tid = threadIdx.x; lane = tid & 31; warp = tid >> 5;
        wm = (warp >> 2) * 64; wn = (warp & 3) * 32;
        row0 = row0_; col0 = col0_;
#pragma unroll
        for (int mt = 0; mt < 4; mt++)
#pragma unroll
            for (int nt = 0; nt < 4; nt++)
#pragma unroll
                for (int i = 0; i < 4; i++) acc[mt][nt][i] = 0.f;
    }

    __device__ __forceinline__ void issue_load(const __half* A, const __half* B,
                                               int K, int stage, int kb) {
        uint32_t sbase = sb + stage * STG1_BYTES;
#pragma unroll
        for (int tile = 0; tile < 2; tile++) {
            const __half* src = (tile == 0) ? A : B;
            int gbase = (tile == 0) ? row0 : col0;
#pragma unroll
            for (int j = 0; j < 2; j++) {
                int s = j * 256 + tid;
                int row = s >> 2;
                int c = (s & 3) << 3;
                const void* g = src + (size_t)(gbase + row) * K + kb + c;
                uint32_t dst = sbase + tile * STG_TILE + (row * ROWP + c) * 2;
                cp_async16(dst, g);
            }
        }
        asm volatile("cp.async.commit_group;" ::: "memory");
    }

    __device__ __forceinline__ void run(const __half* A, const __half* B, int K) {
        const int NI = K / GBK;
        issue_load(A, B, K, 0, 0);
        issue_load(A, B, K, 1, GBK);
        int stage = 0;
        for (int i = 0; i < NI; i++) {
            if (i + 1 < NI) {
                asm volatile("cp.async.wait_group 1;" ::: "memory");
            } else {
                asm volatile("cp.async.wait_group 0;" ::: "memory");
            }
            __syncthreads();
            if (i + 2 < NI) {
                int nstage = stage + 2; if (nstage >= 3) nstage -= 3;
                issue_load(A, B, K, nstage, (i + 2) * GBK);
            }
            const uint32_t sa = sb + stage * STG1_BYTES;
#pragma unroll
            for (int ks = 0; ks < 2; ks++) {
                uint32_t bh[4][2];
#pragma unroll
                for (int np = 0; np < 2; np++) {
                    uint32_t addr = sa + STG_TILE +
                        ((wn + np * 16 + ((lane >> 4) << 3) + (lane & 7)) * ROWP
                         + ks * 16 + (((lane >> 3) & 1) << 3)) * 2;
                    ldm_x4(&bh[np * 2][0], addr);
                }
#pragma unroll
                for (int mt = 0; mt < 4; mt++) {
                    uint32_t ah[4];
                    uint32_t addr = sa +
                        ((wm + mt * 16 + (lane & 15)) * ROWP + ks * 16 + ((lane >> 4) << 3)) * 2;
                    ldm_x4(ah, addr);
#pragma unroll
                    for (int nt = 0; nt < 4; nt++) {
                        mma_f16(acc[mt][nt], ah, bh[nt]);
                    }
                }
            }
            if (++stage == 3) stage = 0;
        }
    }
};

// ---------------- O-projection GEMM (fp32 out) ----------------
__global__ __launch_bounds__(256, 2)
void gemm_f16_1t(const __half* __restrict__ A, const __half* __restrict__ B,
                 float* __restrict__ C, int K, int Ntot) {
    extern __shared__ char smem[];
    GemmCore g;
    g.init(smem_u32(smem), blockIdx.y * 128, blockIdx.x * 128);
    g.run(A, B, K);

#pragma unroll
    for (int mt = 0; mt < 4; mt++) {
#pragma unroll
        for (int nt = 0; nt < 4; nt++) {
            int r = g.row0 + g.wm + mt * 16 + (g.lane >> 2);
            int cidx = g.col0 + g.wn + nt * 8 + ((g.lane & 3) << 1);
            float2* p0 = (float2*)(C + (size_t)r * Ntot + cidx);
            float2* p1 = (float2*)(C + (size_t)(r + 8) * Ntot + cidx);
            *p0 = make_float2(g.acc[mt][nt][0], g.acc[mt][nt][1]);
            *p1 = make_float2(g.acc[mt][nt][2], g.acc[mt][nt][3]);
        }
    }
}

// ---------------- fused QKV GEMM + bias + mROPE + fp16 emit ----------------
// Each CTA covers one head (col0 = head*128). Vectorized __half2 emit:
// lane owns column pair (da, da+1) and (da+64, da+65); warp owns 16 rows.
__global__ __launch_bounds__(256, 2)
void gemm_qkv_rope(const __half* __restrict__ A, const __half* __restrict__ B,
                   const float* __restrict__ bias,
                   const float* __restrict__ cosp, const float* __restrict__ sinp,
                   __half* __restrict__ qh, __half* __restrict__ ql,
                   __half* __restrict__ k16, __half* __restrict__ v16) {
    extern __shared__ char smem[];
    GemmCore g;
    g.init(smem_u32(smem), blockIdx.y * 128, blockIdx.x * 128);
    g.run(A, B, HID);

    // ---- stage acc tile to smem (fp32, stride 132 floats) ----
    __syncthreads();   // all warps done reading pipeline smem
    float* smf = (float*)smem;
#pragma unroll
    for (int mt = 0; mt < 4; mt++) {
#pragma unroll
        for (int nt = 0; nt < 4; nt++) {
            int r = g.wm + mt * 16 + (g.lane >> 2);
            int c = g.wn + nt * 8 + ((g.lane & 3) << 1);
            *(float2*)&smf[r * EP_STRIDE + c]       = make_float2(g.acc[mt][nt][0], g.acc[mt][nt][1]);
            *(float2*)&smf[(r + 8) * EP_STRIDE + c] = make_float2(g.acc[mt][nt][2], g.acc[mt][nt][3]);
        }
    }
    __syncthreads();

    // ---- bias + mROPE + vectorized fp16 emit ----
    const int head = blockIdx.x;                 // 0..35
    const int da = (g.lane) * 2;                 // 0..62 (pairs never cross sec bounds 16/40)
    const int sec = (da < 16) ? 0 : ((da < 40) ? 1 : 2);
    const int SH = S_LEN * HD;
    const float qscale = 0.08838834764831845f * 1.4426950408889634f; // 1/sqrt(128)*log2e

    const float2 b1 = *(const float2*)&bias[g.col0 + da];
    const float2 b2 = *(const float2*)&bias[g.col0 + da + 64];

    if (head < NH) {
#pragma unroll 1
        for (int i = 0; i < 16; i++) {
            int r = g.warp * 16 + i;
            int s = g.row0 + r;
            float2 x1 = *(float2*)&smf[r * EP_STRIDE + da];
            float2 x2 = *(float2*)&smf[r * EP_STRIDE + da + 64];
            x1.x += b1.x; x1.y += b1.y; x2.x += b2.x; x2.y += b2.y;
            float2 c1 = *(const float2*)(cosp + sec * SH + s * HD + da);
            float2 s1 = *(const float2*)(sinp + sec * SH + s * HD + da);
            float2 c2 = *(const float2*)(cosp + sec * SH + s * HD + da + 64);
            float2 s2 = *(const float2*)(sinp + sec * SH + s * HD + da + 64);
            float y1x = (x1.x * c1.x - x2.x * s1.x) * qscale;
            float y1y = (x1.y * c1.y - x2.y * s1.y) * qscale;
            float y2x = (x2.x * c2.x + x1.x * s2.x) * qscale;
            float y2y = (x2.y * c2.y + x1.y * s2.y) * qscale;
            size_t o = (size_t)s * NQD + head * HD;
            __half h1x = __float2half_rn(y1x), h1y = __float2half_rn(y1y);
            __half h2x = __float2half_rn(y2x), h2y = __float2half_rn(y2y);
            *(__half2*)(qh + o + da)      = __halves2half2(h1x, h1y);
            *(__half2*)(qh + o + da + 64) = __halves2half2(h2x, h2y);
            *(__half2*)(ql + o + da)      = __floats2half2_rn(y1x - __half2float(h1x),
                                                              y1y - __half2float(h1y));
            *(__half2*)(ql + o + da + 64) = __floats2half2_rn(y2x - __half2float(h2x),
                                                              y2y - __half2float(h2y));
        }
    } else if (head < NH + NKV) {
        int kvi = head - NH;
#pragma unroll 1
        for (int i = 0; i < 16; i++) {
            int r = g.warp * 16 + i;
            int s = g.row0 + r;
            float2 x1 = *(float2*)&smf[r * EP_STRIDE + da];
            float2 x2 = *(float2*)&smf[r * EP_STRIDE + da + 64];
            x1.x += b1.x; x1.y += b1.y; x2.x += b2.x; x2.y += b2.y;
            float2 c1 = *(const float2*)(cosp + sec * SH + s * HD + da);
            float2 s1 = *(const float2*)(sinp + sec * SH + s * HD + da);
            float2 c2 = *(const float2*)(cosp + sec * SH + s * HD + da + 64);
            float2 s2 = *(const float2*)(sinp + sec * SH + s * HD + da + 64);
            size_t o = (size_t)s * NKD + kvi * HD;
            *(__half2*)(k16 + o + da)      = __floats2half2_rn(x1.x * c1.x - x2.x * s1.x,
                                                               x1.y * c1.y - x2.y * s1.y);
            *(__half2*)(k16 + o + da + 64) = __floats2half2_rn(x2.x * c2.x + x1.x * s2.x,
                                                               x2.y * c2.y + x1.y * s2.y);
        }
    } else {
        int kvi = head - NH - NKV;
#pragma unroll 1
        for (int i = 0; i < 16; i++) {
            int r = g.warp * 16 + i;
            int s = g.row0 + r;
            float2 x1 = *(float2*)&smf[r * EP_STRIDE + da];
            float2 x2 = *(float2*)&smf[r * EP_STRIDE + da + 64];
            size_t o = (size_t)s * NKD + kvi * HD;
            *(__half2*)(v16 + o + da)      = __floats2half2_rn(x1.x + b1.x, x1.y + b1.y);
            *(__half2*)(v16 + o + da + 64) = __floats2half2_rn(x2.x + b2.x, x2.y + b2.y);
        }
    }
}

// ---------------- attention: fp16 mma flash, BN=64, QK 2-term / PV 1-term ----------------
#define ATP 136
#define AT_ROWB (ATP*2)              // 272 B/row
#define AQ_TILE (128*AT_ROWB)        // 34816
#define KV_TILE (64*AT_ROWB)         // 17408
#define KV_STG  (2*KV_TILE)          // 34816 (K, V)
#define AQ_H 0
#define AQ_L AQ_TILE
#define AKV  (2*AQ_TILE)
#define ATTN_SMEM (AKV + 2*KV_STG)   // 139264 B

__global__ __launch_bounds__(256)
void attn_mma(const __half* __restrict__ qh, const __half* __restrict__ ql,
              const __half* __restrict__ k16, const __half* __restrict__ v16,
              __half* __restrict__ ctx16) {
    extern __shared__ char smem[];
    const uint32_t sb = smem_u32(smem);
    const int tid = threadIdx.x;
    const int lane = tid & 31;
    const int warp = tid >> 5;           // 0..7
    const int h = blockIdx.y;
    const int kvh = h / GRP;
    const int r0 = blockIdx.x * 128;

#pragma unroll
    for (int j = 0; j < 8; j++) {
        int idx = j * 256 + tid;
        int row = idx >> 4, c = idx & 15;
        size_t g = (size_t)(r0 + row) * NQD + h * HD + c * 8;
        uint32_t so = row * AT_ROWB + c * 16;
        cp_async16(sb + AQ_H + so, qh + g);
        cp_async16(sb + AQ_L + so, ql + g);
    }
    asm volatile("cp.async.commit_group;" ::: "memory");

    auto issue_kv = [&](int stage, int kt) {
        uint32_t base = sb + AKV + stage * KV_STG;
#pragma unroll
        for (int j = 0; j < 4; j++) {
            int idx = j * 256 + tid;
            int row = idx >> 4, c = idx & 15;
            size_t g = (size_t)(kt + row) * NKD + kvh * HD + c * 8;
            uint32_t so = row * AT_ROWB + c * 16;
            cp_async16(base + 0 * KV_TILE + so, k16 + g);
            cp_async16(base + 1 * KV_TILE + so, v16 + g);
        }
        asm volatile("cp.async.commit_group;" ::: "memory");
    };

    issue_kv(0, 0);
    asm volatile("cp.async.wait_group 1;" ::: "memory");
    __syncthreads();

    uint32_t qfh[8][4], qfl[8][4];
#pragma unroll
    for (int kf = 0; kf < 8; kf++) {
        uint32_t off = ((warp * 16 + (lane & 15)) * ATP + kf * 16 + ((lane >> 4) << 3)) * 2;
        ldm_x4(qfh[kf], sb + AQ_H + off);
        ldm_x4(qfl[kf], sb + AQ_L + off);
    }

    float o[16][4];
#pragma unroll
    for (int nt = 0; nt < 16; nt++)
#pragma unroll
        for (int i = 0; i < 4; i++) o[nt][i] = 0.f;
    float m0 = -INFINITY, m1 = -INFINITY, l0 = 0.f, l1 = 0.f;

    const int NI = S_LEN / 64;            // 32

    for (int it = 0; it < NI; it++) {
        asm volatile("cp.async.wait_group 0;" ::: "memory");
        __syncthreads();
        if (it + 1 < NI) issue_kv((it + 1) & 1, (it + 1) * 64);

        const uint32_t sk = sb + AKV + (it & 1) * KV_STG;

        float s[8][4];
#pragma unroll
        for (int nt = 0; nt < 8; nt++)
#pragma unroll
            for (int i = 0; i < 4; i++) s[nt][i] = 0.f;

#pragma unroll
        for (int kf = 0; kf < 8; kf++) {
            uint32_t kb[8][2];
#pragma unroll
            for (int np = 0; np < 4; np++) {
                uint32_t addr = sk +
                    ((np * 16 + ((lane >> 4) << 3) + (lane & 7)) * ATP
                     + kf * 16 + (((lane >> 3) & 1) << 3)) * 2;
                ldm_x4(&kb[np * 2][0], addr);
            }
#pragma unroll
            for (int nt = 0; nt < 8; nt++) {
                mma_f16(s[nt], qfh[kf], kb[nt]);
                mma_f16(s[nt], qfl[kf], kb[nt]);
            }
        }

        float mx0 = -INFINITY, mx1 = -INFINITY;
#pragma unroll
        for (int nt = 0; nt < 8; nt++) {
            mx0 = fmaxf(mx0, fmaxf(s[nt][0], s[nt][1]));
            mx1 = fmaxf(mx1, fmaxf(s[nt][2], s[nt][3]));
        }
        mx0 = fmaxf(mx0, __shfl_xor_sync(0xffffffffu, mx0, 1));
        mx0 = fmaxf(mx0, __shfl_xor_sync(0xffffffffu, mx0, 2));
        mx1 = fmaxf(mx1, __shfl_xor_sync(0xffffffffu, mx1, 1));
        mx1 = fmaxf(mx1, __shfl_xor_sync(0xffffffffu, mx1, 2));

        float nm0 = fmaxf(m0, mx0), nm1 = fmaxf(m1, mx1);
        float c0 = fexp2(m0 - nm0), c1 = fexp2(m1 - nm1);
        m0 = nm0; m1 = nm1;

        float sum0 = 0.f, sum1 = 0.f;
#pragma unroll
        for (int nt = 0; nt < 8; nt++) {
            s[nt][0] = fexp2(s[nt][0] - nm0);
            s[nt][1] = fexp2(s[nt][1] - nm0);
            s[nt][2] = fexp2(s[nt][2] - nm1);
            s[nt][3] = fexp2(s[nt][3] - nm1);
            sum0 += s[nt][0] + s[nt][1];
            sum1 += s[nt][2] + s[nt][3];
        }
        sum0 += __shfl_xor_sync(0xffffffffu, sum0, 1);
        sum0 += __shfl_xor_sync(0xffffffffu, sum0, 2);
        sum1 += __shfl_xor_sync(0xffffffffu, sum1, 1);
        sum1 += __shfl_xor_sync(0xffffffffu, sum1, 2);
        l0 = l0 * c0 + sum0;
        l1 = l1 * c1 + sum1;

#pragma unroll
        for (int nt = 0; nt < 16; nt++) {
            o[nt][0] *= c0; o[nt][1] *= c0;
            o[nt][2] *= c1; o[nt][3] *= c1;
        }

#pragma unroll
        for (int kf = 0; kf < 4; kf++) {
            uint32_t ah[4];
#pragma unroll
            for (int half = 0; half < 2; half++) {
                int nt = 2 * kf + half;
                ah[2 * half]     = pack_h2(s[nt][0], s[nt][1]);
                ah[2 * half + 1] = pack_h2(s[nt][2], s[nt][3]);
            }
#pragma unroll
            for (int np = 0; np < 8; np++) {
                uint32_t vb[4];
                uint32_t addr = sk + KV_TILE +
                    ((kf * 16 + (lane & 15)) * ATP + np * 16 + ((lane >> 4) << 3)) * 2;
                ldm_x4_t(vb, addr);
                mma_f16(o[2 * np],     ah, &vb[0]);
                mma_f16(o[2 * np + 1], ah, &vb[2]);
            }
        }
    }

    float inv0 = 1.f / l0, inv1 = 1.f / l1;
    int r_lo = r0 + warp * 16 + (lane >> 2);
    int r_hi = r_lo + 8;
#pragma unroll
    for (int nt = 0; nt < 16; nt++) {
        int col = h * HD + nt * 8 + ((lane & 3) << 1);
        *(__half2*)(ctx16 + (size_t)r_lo * NQD + col) =
            __floats2half2_rn(o[nt][0] * inv0, o[nt][1] * inv0);
        *(__half2*)(ctx16 + (size_t)r_hi * NQD + col) =
            __floats2half2_rn(o[nt][2] * inv1, o[nt][3] * inv1);
    }
}

// ---------------- launch ----------------
extern "C" void kernel_launch(void* const* d_in, const int* in_sizes, int n_in,
                              void* d_out, int out_size) {
    const float* hs   = (const float*)d_in[0];
    const float* cosp = (const float*)d_in[1];
    const float* sinp = (const float*)d_in[2];
    const float* Wq   = (const float*)d_in[3];
    const float* bq   = (const float*)d_in[4];
    const float* Wk   = (const float*)d_in[5];
    const float* bk   = (const float*)d_in[6];
    const float* Wv   = (const float*)d_in[7];
    const float* bv   = (const float*)d_in[8];
    const float* Wo   = (const float*)d_in[9];
    float* out = (float*)d_out;

    float* bias_p;
    cudaGetSymbolAddress((void**)&bias_p, g_bias);

    __half *hs16, *w16, *wo16, *ctx16, *q16h, *q16l, *k16, *v16;
    cudaGetSymbolAddress((void**)&hs16,  g_hs16);
    cudaGetSymbolAddress((void**)&ctx16, g_ctx16);
    cudaGetSymbolAddress((void**)&w16,   g_w16);  cudaGetSymbolAddress((void**)&wo16, g_wo16);
    cudaGetSymbolAddress((void**)&q16h,  g_q16h); cudaGetSymbolAddress((void**)&q16l, g_q16l);
    cudaGetSymbolAddress((void**)&k16,   g_k16);  cudaGetSymbolAddress((void**)&v16,  g_v16);

    cudaFuncSetAttribute(gemm_f16_1t,   cudaFuncAttributeMaxDynamicSharedMemorySize, GEMM1_SMEM);
    cudaFuncSetAttribute(gemm_qkv_rope, cudaFuncAttributeMaxDynamicSharedMemorySize, FUSED_SMEM);
    cudaFuncSetAttribute(attn_mma,      cudaFuncAttributeMaxDynamicSharedMemorySize, ATTN_SMEM);

    // 1) input convert + weight transposes (all fp16) + bias concat
    {
        int n4 = S_LEN * HID / 4;
        conv_h_kernel<<<(n4 + 255) / 256, 256>>>((const float4*)hs, (__half2*)hs16, n4);
    }
    {
        dim3 blk(32, 8);
        tsplit2h_kernel<<<dim3(NQD / 32, HID / 64), blk>>>(Wq, w16, HID, NQD);
        tsplit2h_kernel<<<dim3(NKD / 32, HID / 64), blk>>>(Wk, w16 + (size_t)NQD * HID, HID, NKD);
        tsplit2h_kernel<<<dim3(NKD / 32, HID / 64), blk>>>(Wv, w16 + (size_t)(NQD + NKD) * HID, HID, NKD);
        tsplit2h_kernel<<<dim3(HID / 32, NQD / 64), blk>>>(Wo, wo16, NQD, HID);
        concat_bias_kernel<<<(NQKV + 255) / 256, 256>>>(bq, bk, bv, bias_p);
    }

    // 2) fused QKV projection + bias + mROPE + fp16 emit (vectorized)
    gemm_qkv_rope<<<dim3(NQKV / 128, S_LEN / 128), 256, FUSED_SMEM>>>(
        hs16, w16, bias_p, cosp, sinp, q16h, q16l, k16, v16);

    // 3) attention -> ctx (single fp16)
    {
        dim3 grid(S_LEN / 128, NH);
        attn_mma<<<grid, 256, ATTN_SMEM>>>(q16h, q16l, k16, v16, ctx16);
    }

    // 4) output projection (fp16 1-term)
    gemm_f16_1t<<<dim3(HID / 128, S_LEN / 128), 256, GEMM1_SMEM>>>(ctx16, wo16, out, NQD, HID);
}

// round 16
// speedup vs baseline: 1.5559x; 1.5559x over previous
#include <cuda_runtime.h>
#include <cuda_fp16.h>
#include <math.h>
#include <stdint.h>

// ---------------- problem constants ----------------
#define S_LEN 2048
#define HID   3584
#define NH    28
#define NKV   4
#define HD    128
#define NQD   (NH*HD)    // 3584
#define NKD   (NKV*HD)   // 512
#define GRP   (NH/NKV)   // 7
#define NQKV  (NQD + 2*NKD)  // 4608

// ---------------- scratch (device globals; no allocs allowed) ----------------
__device__ float g_qkv[(size_t)S_LEN * NQKV];
__device__ float g_bias[NQKV];

__device__ __align__(16) __half g_hs16[S_LEN * HID];
__device__ __align__(16) __half g_ctx16[S_LEN * NQD];
__device__ __align__(16) __half g_q16h[S_LEN * NQD], g_q16l[S_LEN * NQD];
__device__ __align__(16) __half g_k16[S_LEN * NKD];
__device__ __align__(16) __half g_v16[S_LEN * NKD];
__device__ __align__(16) __half g_w16[(size_t)NQKV * HID];
__device__ __align__(16) __half g_wo16[(size_t)HID * NQD];

// ---------------- helpers ----------------
__device__ __forceinline__ uint32_t smem_u32(const void* p) {
    uint32_t a;
    asm("{ .reg .u64 t; cvta.to.shared.u64 t, %1; cvt.u32.u64 %0, t; }" : "=r"(a) : "l"(p));
    return a;
}

__device__ __forceinline__ void cp_async16(uint32_t dst, const void* src) {
    asm volatile("cp.async.cg.shared.global [%0], [%1], 16;" :: "r"(dst), "l"(src) : "memory");
}

__device__ __forceinline__ void ldm_x4(uint32_t* r, uint32_t addr) {
    asm volatile("ldmatrix.sync.aligned.m8n8.x4.shared.b16 {%0,%1,%2,%3}, [%4];"
                 : "=r"(r[0]), "=r"(r[1]), "=r"(r[2]), "=r"(r[3]) : "r"(addr));
}

__device__ __forceinline__ void ldm_x4_t(uint32_t* r, uint32_t addr) {
    asm volatile("ldmatrix.sync.aligned.m8n8.x4.trans.shared.b16 {%0,%1,%2,%3}, [%4];"
                 : "=r"(r[0]), "=r"(r[1]), "=r"(r[2]), "=r"(r[3]) : "r"(addr));
}

__device__ __forceinline__ void mma_f16(float* c, const uint32_t* a, const uint32_t* b) {
    asm volatile(
        "mma.sync.aligned.m16n8k16.row.col.f32.f16.f16.f32 "
        "{%0,%1,%2,%3}, {%4,%5,%6,%7}, {%8,%9}, {%0,%1,%2,%3};"
        : "+f"(c[0]), "+f"(c[1]), "+f"(c[2]), "+f"(c[3])
        : "r"(a[0]), "r"(a[1]), "r"(a[2]), "r"(a[3]), "r"(b[0]), "r"(b[1]));
}

__device__ __forceinline__ uint32_t pack_h2(float a, float b) {
    __half2 h = __floats2half2_rn(a, b);
    return *(uint32_t*)&h;
}

__device__ __forceinline__ float fexp2(float x) {
    float r;
    asm("ex2.approx.f32 %0, %1;" : "=f"(r) : "f"(x));
    return r;
}

// ---------------- convert kernels ----------------
__global__ void conv_h_kernel(const float4* __restrict__ X, __half2* __restrict__ H, int n4) {
    int i = blockIdx.x * 256 + threadIdx.x;
    if (i >= n4) return;
    float4 x = X[i];
    H[2*i]   = __floats2half2_rn(x.x, x.y);
    H[2*i+1] = __floats2half2_rn(x.z, x.w);
}

// merged QKV weight transpose: W [HID,N] fp32 -> T [N,HID] fp16 at per-weight offsets.
// grid.x: 0-111 -> Wq (NQD), 112-127 -> Wk, 128-143 -> Wv
__global__ void tsplit_qkv_kernel(const float* __restrict__ Wq, const float* __restrict__ Wk,
                                  const float* __restrict__ Wv, __half* __restrict__ T) {
    __shared__ float t[64][33];
    int bx = blockIdx.x;
    const float* W; int N; int n0; size_t tb;
    if (bx < 112)      { W = Wq; N = NQD; n0 = bx * 32;         tb = 0; }
    else if (bx < 128) { W = Wk; N = NKD; n0 = (bx - 112) * 32; tb = (size_t)NQD * HID; }
    else               { W = Wv; N = NKD; n0 = (bx - 128) * 32; tb = (size_t)(NQD + NKD) * HID; }
    int k0 = blockIdx.y * 64;
    int tx = threadIdx.x, ty = threadIdx.y;
#pragma unroll
    for (int i = 0; i < 8; i++) {
        int k = i * 8 + ty;
        t[k][tx] = W[(size_t)(k0 + k) * N + n0 + tx];
    }
    __syncthreads();
#pragma unroll
    for (int i = 0; i < 4; i++) {
        int n = i * 8 + ty;
        __half2 hp = __floats2half2_rn(t[2 * tx][n], t[2 * tx + 1][n]);
        *(__half2*)(T + tb + (size_t)(n0 + n) * HID + k0 + 2 * tx) = hp;
    }
}

// W [K,N] fp32 row-major -> T [N,K] fp16 (single). Tile 32n x 64k, block (32,8).
__global__ void tsplit2h_kernel(const float* __restrict__ W, __half* __restrict__ T,
                                int K, int N) {
    __shared__ float t[64][33];
    int n0 = blockIdx.x * 32, k0 = blockIdx.y * 64;
    int tx = threadIdx.x, ty = threadIdx.y;
#pragma unroll
    for (int i = 0; i < 8; i++) {
        int k = i * 8 + ty;
        t[k][tx] = W[(size_t)(k0 + k) * N + n0 + tx];
    }
    __syncthreads();
#pragma unroll
    for (int i = 0; i < 4; i++) {
        int n = i * 8 + ty;
        __half2 hp = __floats2half2_rn(t[2 * tx][n], t[2 * tx + 1][n]);
        *(__half2*)(T + (size_t)(n0 + n) * K + k0 + 2 * tx) = hp;
    }
}

__global__ void concat_bias_kernel(const float* __restrict__ bq, const float* __restrict__ bk,
                                   const float* __restrict__ bv, float* __restrict__ b) {
    int i = blockIdx.x * 256 + threadIdx.x;
    if (i < NQD) b[i] = bq[i];
    else if (i < NQD + NKD) b[i] = bk[i - NQD];
    else if (i < NQKV) b[i] = bv[i - NQD - NKD];
}

// ---------------- mma.sync GEMM (fp16 1-term: A x B) ----------------
#define GBK 32
#define ROWP 40
#define STG_TILE (128*ROWP*2)          // 10240 B per operand tile
#define STG1_BYTES (2*STG_TILE)        // 20480 B per stage (A, B)
#define GEMM1_SMEM (3*STG1_BYTES)      // 61440 B (3 stages)

__global__ __launch_bounds__(256, 2)
void gemm_f16_1t(const __half* __restrict__ A, const __half* __restrict__ B,
                 const float* __restrict__ bias,
                 float* __restrict__ C, int K, int Ntot) {
    extern __shared__ char smem[];
    const uint32_t sb = smem_u32(smem);
    const int tid = threadIdx.x;
    const int lane = tid & 31;
    const int warp = tid >> 5;
    const int wm = (warp >> 2) * 64;
    const int wn = (warp & 3) * 32;
    const int row0 = blockIdx.y * 128;
    const int col0 = blockIdx.x * 128;
    const int NI = K / GBK;

    float acc[4][4][4];
#pragma unroll
    for (int mt = 0; mt < 4; mt++)
#pragma unroll
        for (int nt = 0; nt < 4; nt++)
#pragma unroll
            for (int i = 0; i < 4; i++) acc[mt][nt][i] = 0.f;

    auto issue_load = [&](int stage, int kb) {
        uint32_t sbase = sb + stage * STG1_BYTES;
#pragma unroll
        for (int tile = 0; tile < 2; tile++) {
            const __half* src = (tile == 0) ? A : B;
            int gbase = (tile == 0) ? row0 : col0;
#pragma unroll
            for (int j = 0; j < 2; j++) {
                int s = j * 256 + tid;
                int row = s >> 2;
                int c = (s & 3) << 3;
                const void* g = src + (size_t)(gbase + row) * K + kb + c;
                uint32_t dst = sbase + tile * STG_TILE + (row * ROWP + c) * 2;
                cp_async16(dst, g);
            }
        }
        asm volatile("cp.async.commit_group;" ::: "memory");
    };

    issue_load(0, 0);
    issue_load(1, GBK);

    int stage = 0;
    for (int i = 0; i < NI; i++) {
        if (i + 1 < NI) {
            asm volatile("cp.async.wait_group 1;" ::: "memory");
        } else {
            asm volatile("cp.async.wait_group 0;" ::: "memory");
        }
        __syncthreads();
        if (i + 2 < NI) {
            int nstage = stage + 2; if (nstage >= 3) nstage -= 3;
            issue_load(nstage, (i + 2) * GBK);
        }

        const uint32_t sa = sb + stage * STG1_BYTES;
#pragma unroll
        for (int ks = 0; ks < 2; ks++) {
            uint32_t bh[4][2];
#pragma unroll
            for (int np = 0; np < 2; np++) {
                uint32_t addr = sa + STG_TILE +
                    ((wn + np * 16 + ((lane >> 4) << 3) + (lane & 7)) * ROWP
                     + ks * 16 + (((lane >> 3) & 1) << 3)) * 2;
                ldm_x4(&bh[np * 2][0], addr);
            }
#pragma unroll
            for (int mt = 0; mt < 4; mt++) {
                uint32_t ah[4];
                uint32_t addr = sa +
                    ((wm + mt * 16 + (lane & 15)) * ROWP + ks * 16 + ((lane >> 4) << 3)) * 2;
                ldm_x4(ah, addr);
#pragma unroll
                for (int nt = 0; nt < 4; nt++) {
                    mma_f16(acc[mt][nt], ah, bh[nt]);
                }
            }
        }
        if (++stage == 3) stage = 0;
    }

#pragma unroll
    for (int mt = 0; mt < 4; mt++) {
#pragma unroll
        for (int nt = 0; nt < 4; nt++) {
            int r = row0 + wm + mt * 16 + (lane >> 2);
            int cidx = col0 + wn + nt * 8 + ((lane & 3) << 1);
            float b0 = 0.f, b1 = 0.f;
            if (bias) { b0 = bias[cidx]; b1 = bias[cidx + 1]; }
            float2* p0 = (float2*)(C + (size_t)r * Ntot + cidx);
            float2* p1 = (float2*)(C + (size_t)(r + 8) * Ntot + cidx);
            *p0 = make_float2(acc[mt][nt][0] + b0, acc[mt][nt][1] + b1);
            *p1 = make_float2(acc[mt][nt][2] + b0, acc[mt][nt][3] + b1);
        }
    }
}

// ---------------- fused mROPE + fp16 split ----------------
// q -> fp16 hi/lo (scaled by 1/sqrt(HD) * log2(e)), k -> fp16 single, v -> fp16 single
__global__ __launch_bounds__(256)
void rope_split_kernel(const float* __restrict__ qkv,
                       const float* __restrict__ cosp, const float* __restrict__ sinp,
                       __half* __restrict__ qh, __half* __restrict__ ql,
                       __half* __restrict__ k16, __half* __restrict__ v16) {
    const int s = blockIdx.x;
    const int lane = threadIdx.x & 31;
    const int grp = threadIdx.x >> 5;     // 0..7
    const int da = 2 * lane;              // even, 0..62
    const int sec = (da < 16) ? 0 : ((da < 40) ? 1 : 2);
    const int SH = S_LEN * HD;
    // 1/sqrt(128) * log2(e): exp folded to exp2
    const float scale = 0.08838834764831845f * 1.4426950408889634f;

    const float2 c1 = *(const float2*)(cosp + sec * SH + s * HD + da);
    const float2 s1 = *(const float2*)(sinp + sec * SH + s * HD + da);
    const float2 c2 = *(const float2*)(cosp + sec * SH + s * HD + da + 64);
    const float2 s2 = *(const float2*)(sinp + sec * SH + s * HD + da + 64);

    const float* row = qkv + (size_t)s * NQKV;

    auto store2h = [](__half* H, __half* L, size_t o, float a, float b) {
        __half ha = __float2half_rn(a), hb = __float2half_rn(b);
        *(__half2*)(H + o) = __halves2half2(ha, hb);
        *(__half2*)(L + o) = __floats2half2_rn(a - __half2float(ha), b - __half2float(hb));
    };

#pragma unroll 1
    for (int it = 0; it < 5; it++) {
        int hh = it * 8 + grp;    // 0..39, valid < 36
        if (hh >= NH + 2 * NKV) break;
        if (hh < NH) {
            const float* base = row + hh * HD;
            float2 x1 = *(const float2*)(base + da);
            float2 x2 = *(const float2*)(base + da + 64);
            size_t o = (size_t)s * NQD + hh * HD;
            store2h(qh, ql, o + da,      (x1.x * c1.x - x2.x * s1.x) * scale,
                                         (x1.y * c1.y - x2.y * s1.y) * scale);
            store2h(qh, ql, o + da + 64, (x2.x * c2.x + x1.x * s2.x) * scale,
                                         (x2.y * c2.y + x1.y * s2.y) * scale);
        } else if (hh < NH + NKV) {
            int kvi = hh - NH;
            const float* base = row + NQD + kvi * HD;
            float2 x1 = *(const float2*)(base + da);
            float2 x2 = *(const float2*)(base + da + 64);
            size_t o = (size_t)s * NKD + kvi * HD;
            *(__half2*)(k16 + o + da)      = __floats2half2_rn(x1.x * c1.x - x2.x * s1.x,
                                                               x1.y * c1.y - x2.y * s1.y);
            *(__half2*)(k16 + o + da + 64) = __floats2half2_rn(x2.x * c2.x + x1.x * s2.x,
                                                               x2.y * c2.y + x1.y * s2.y);
        } else {
            int kvi = hh - NH - NKV;
            const float* base = row + NQD + NKD + kvi * HD;
            float2 x1 = *(const float2*)(base + da);
            float2 x2 = *(const float2*)(base + da + 64);
            size_t o = (size_t)s * NKD + kvi * HD;
            *(__half2*)(v16 + o + da)      = __floats2half2_rn(x1.x, x1.y);
            *(__half2*)(v16 + o + da + 64) = __floats2half2_rn(x2.x, x2.y);
        }
    }
}

// ---------------- attention: fp16 mma flash, BN=64, QK 2-term / PV 1-term ----------------
#define ATP 136
#define AT_ROWB (ATP*2)              // 272 B/row
#define AQ_TILE (128*AT_ROWB)        // 34816
#define KV_TILE (64*AT_ROWB)         // 17408 (64 keys x 128 dims)
#define KV_STG  (2*KV_TILE)          // 34816 (K, V)
#define AQ_H 0
#define AQ_L AQ_TILE
#define AKV  (2*AQ_TILE)
#define ATTN_SMEM (AKV + 2*KV_STG)   // 139264 B

__global__ __launch_bounds__(256)
void attn_mma(const __half* __restrict__ qh, const __half* __restrict__ ql,
              const __half* __restrict__ k16, const __half* __restrict__ v16,
              __half* __restrict__ ctx16) {
    extern __shared__ char smem[];
    const uint32_t sb = smem_u32(smem);
    const int tid = threadIdx.x;
    const int lane = tid & 31;
    const int warp = tid >> 5;           // 0..7
    const int h = blockIdx.y;
    const int kvh = h / GRP;
    const int r0 = blockIdx.x * 128;

    // ---- Q tile (128 x 128) hi/lo ----
#pragma unroll
    for (int j = 0; j < 8; j++) {
        int idx = j * 256 + tid;          // 0..2047
        int row = idx >> 4, c = idx & 15;
        size_t g = (size_t)(r0 + row) * NQD + h * HD + c * 8;
        uint32_t so = row * AT_ROWB + c * 16;
        cp_async16(sb + AQ_H + so, qh + g);
        cp_async16(sb + AQ_L + so, ql + g);
    }
    asm volatile("cp.async.commit_group;" ::: "memory");

    auto issue_kv = [&](int stage, int kt) {
        uint32_t base = sb + AKV + stage * KV_STG;
#pragma unroll
        for (int j = 0; j < 4; j++) {
            int idx = j * 256 + tid;      // 0..1023
            int row = idx >> 4, c = idx & 15;
            size_t g = (size_t)(kt + row) * NKD + kvh * HD + c * 8;
            uint32_t so = row * AT_ROWB + c * 16;
            cp_async16(base + 0 * KV_TILE + so, k16 + g);
            cp_async16(base + 1 * KV_TILE + so, v16 + g);
        }
        asm volatile("cp.async.commit_group;" ::: "memory");
    };

    issue_kv(0, 0);
    asm volatile("cp.async.wait_group 1;" ::: "memory");   // Q done (kv0 may pend)
    __syncthreads();

    // ---- Q fragments (warp owns rows [warp*16, warp*16+16)) ----
    uint32_t qfh[8][4], qfl[8][4];
#pragma unroll
    for (int kf = 0; kf < 8; kf++) {
        uint32_t off = ((warp * 16 + (lane & 15)) * ATP + kf * 16 + ((lane >> 4) << 3)) * 2;
        ldm_x4(qfh[kf], sb + AQ_H + off);
        ldm_x4(qfl[kf], sb + AQ_L + off);
    }

    float o[16][4];
#pragma unroll
    for (int nt = 0; nt < 16; nt++)
#pragma unroll
        for (int i = 0; i < 4; i++) o[nt][i] = 0.f;
    float m0 = -INFINITY, m1 = -INFINITY, l0 = 0.f, l1 = 0.f;

    const int NI = S_LEN / 64;            // 32

    for (int it = 0; it < NI; it++) {
        asm volatile("cp.async.wait_group 0;" ::: "memory");  // kv stage `it` landed
        __syncthreads();   // stage visible; compute(it-1) done block-wide
        if (it + 1 < NI) issue_kv((it + 1) & 1, (it + 1) * 64);

        const uint32_t sk = sb + AKV + (it & 1) * KV_STG;

        // ---- S = Q K^T (2-term: Qh*K + Ql*K), 64 keys = 8 n-tiles ----
        float s[8][4];
#pragma unroll
        for (int nt = 0; nt < 8; nt++)
#pragma unroll
            for (int i = 0; i < 4; i++) s[nt][i] = 0.f;

#pragma unroll
        for (int kf = 0; kf < 8; kf++) {
            uint32_t kb[8][2];
#pragma unroll
            for (int np = 0; np < 4; np++) {
                uint32_t addr = sk +
                    ((np * 16 + ((lane >> 4) << 3) + (lane & 7)) * ATP
                     + kf * 16 + (((lane >> 3) & 1) << 3)) * 2;
                ldm_x4(&kb[np * 2][0], addr);
            }
#pragma unroll
            for (int nt = 0; nt < 8; nt++) {
                mma_f16(s[nt], qfh[kf], kb[nt]);
                mma_f16(s[nt], qfl[kf], kb[nt]);
            }
        }

        // ---- online softmax (base-2; log2e folded into q scale) ----
        float mx0 = -INFINITY, mx1 = -INFINITY;
#pragma unroll
        for (int nt = 0; nt < 8; nt++) {
            mx0 = fmaxf(mx0, fmaxf(s[nt][0], s[nt][1]));
            mx1 = fmaxf(mx1, fmaxf(s[nt][2], s[nt][3]));
        }
        mx0 = fmaxf(mx0, __shfl_xor_sync(0xffffffffu, mx0, 1));
        mx0 = fmaxf(mx0, __shfl_xor_sync(0xffffffffu, mx0, 2));
        mx1 = fmaxf(mx1, __shfl_xor_sync(0xffffffffu, mx1, 1));
        mx1 = fmaxf(mx1, __shfl_xor_sync(0xffffffffu, mx1, 2));

        float nm0 = fmaxf(m0, mx0), nm1 = fmaxf(m1, mx1);
        float c0 = fexp2(m0 - nm0), c1 = fexp2(m1 - nm1);
        m0 = nm0; m1 = nm1;

        float sum0 = 0.f, sum1 = 0.f;
#pragma unroll
        for (int nt = 0; nt < 8; nt++) {
            s[nt][0] = fexp2(s[nt][0] - nm0);
            s[nt][1] = fexp2(s[nt][1] - nm0);
            s[nt][2] = fexp2(s[nt][2] - nm1);
            s[nt][3] = fexp2(s[nt][3] - nm1);
            sum0 += s[nt][0] + s[nt][1];
            sum1 += s[nt][2] + s[nt][3];
        }
        sum0 += __shfl_xor_sync(0xffffffffu, sum0, 1);
        sum0 += __shfl_xor_sync(0xffffffffu, sum0, 2);
        sum1 += __shfl_xor_sync(0xffffffffu, sum1, 1);
        sum1 += __shfl_xor_sync(0xffffffffu, sum1, 2);
        l0 = l0 * c0 + sum0;
        l1 = l1 * c1 + sum1;

#pragma unroll
        for (int nt = 0; nt < 16; nt++) {
            o[nt][0] *= c0; o[nt][1] *= c0;
            o[nt][2] *= c1; o[nt][3] *= c1;
        }

        // ---- O += P V (1-term; P single fp16), 64 keys = kf 0..3 ----
#pragma unroll
        for (int kf = 0; kf < 4; kf++) {
            uint32_t ah[4];
#pragma unroll
            for (int half = 0; half < 2; half++) {
                int nt = 2 * kf + half;
                ah[2 * half]     = pack_h2(s[nt][0], s[nt][1]);
                ah[2 * half + 1] = pack_h2(s[nt][2], s[nt][3]);
            }
#pragma unroll
            for (int np = 0; np < 8; np++) {
                uint32_t vb[4];
                uint32_t addr = sk + KV_TILE +
                    ((kf * 16 + (lane & 15)) * ATP + np * 16 + ((lane >> 4) << 3)) * 2;
                ldm_x4_t(vb, addr);
                mma_f16(o[2 * np],     ah, &vb[0]);
                mma_f16(o[2 * np + 1], ah, &vb[2]);
            }
        }
    }

    // ---- epilogue: ctx as single fp16 ----
    float inv0 = 1.f / l0, inv1 = 1.f / l1;
    int r_lo = r0 + warp * 16 + (lane >> 2);
    int r_hi = r_lo + 8;
#pragma unroll
    for (int nt = 0; nt < 16; nt++) {
        int col = h * HD + nt * 8 + ((lane & 3) << 1);
        *(__half2*)(ctx16 + (size_t)r_lo * NQD + col) =
            __floats2half2_rn(o[nt][0] * inv0, o[nt][1] * inv0);
        *(__half2*)(ctx16 + (size_t)r_hi * NQD + col) =
            __floats2half2_rn(o[nt][2] * inv1, o[nt][3] * inv1);
    }
}

// ---------------- launch ----------------
extern "C" void kernel_launch(void* const* d_in, const int* in_sizes, int n_in,
                              void* d_out, int out_size) {
    const float* hs   = (const float*)d_in[0];
    const float* cosp = (const float*)d_in[1];
    const float* sinp = (const float*)d_in[2];
    const float* Wq   = (const float*)d_in[3];
    const float* bq   = (const float*)d_in[4];
    const float* Wk   = (const float*)d_in[5];
    const float* bk   = (const float*)d_in[6];
    const float* Wv   = (const float*)d_in[7];
    const float* bv   = (const float*)d_in[8];
    const float* Wo   = (const float*)d_in[9];
    float* out = (float*)d_out;

    float *qkv_p, *bias_p;
    cudaGetSymbolAddress((void**)&qkv_p,  g_qkv);
    cudaGetSymbolAddress((void**)&bias_p, g_bias);

    __half *hs16, *w16, *wo16, *ctx16, *q16h, *q16l, *k16, *v16;
    cudaGetSymbolAddress((void**)&hs16,  g_hs16);
    cudaGetSymbolAddress((void**)&ctx16, g_ctx16);
    cudaGetSymbolAddress((void**)&w16,   g_w16);  cudaGetSymbolAddress((void**)&wo16, g_wo16);
    cudaGetSymbolAddress((void**)&q16h,  g_q16h); cudaGetSymbolAddress((void**)&q16l, g_q16l);
    cudaGetSymbolAddress((void**)&k16,   g_k16);  cudaGetSymbolAddress((void**)&v16,  g_v16);

    cudaFuncSetAttribute(gemm_f16_1t, cudaFuncAttributeMaxDynamicSharedMemorySize, GEMM1_SMEM);
    cudaFuncSetAttribute(attn_mma,    cudaFuncAttributeMaxDynamicSharedMemorySize, ATTN_SMEM);

    // 1) input convert + weight transposes (all fp16) + bias concat
    {
        int n4 = S_LEN * HID / 4;
        conv_h_kernel<<<(n4 + 255) / 256, 256>>>((const float4*)hs, (__half2*)hs16, n4);
    }
    {
        dim3 blk(32, 8);
        tsplit_qkv_kernel<<<dim3(144, HID / 64), blk>>>(Wq, Wk, Wv, w16);
        tsplit2h_kernel<<<dim3(HID / 32, NQD / 64), blk>>>(Wo, wo16, NQD, HID);
        concat_bias_kernel<<<(NQKV + 255) / 256, 256>>>(bq, bk, bv, bias_p);
    }

    // 2) fused QKV projection (fp16 1-term)
    gemm_f16_1t<<<dim3(NQKV / 128, S_LEN / 128), 256, GEMM1_SMEM>>>(hs16, w16, bias_p, qkv_p, HID, NQKV);

    // 3) fused mROPE + fp16 split (q hi/lo scaled with log2e folded; k,v single)
    rope_split_kernel<<<S_LEN, 256>>>(qkv_p, cosp, sinp, q16h, q16l, k16, v16);

    // 4) attention -> ctx (single fp16)
    {
        dim3 grid(S_LEN / 128, NH);
        attn_mma<<<grid, 256, ATTN_SMEM>>>(q16h, q16l, k16, v16, ctx16);
    }

    // 5) output projection (fp16 1-term)
    gemm_f16_1t<<<dim3(HID / 128, S_LEN / 128), 256, GEMM1_SMEM>>>(ctx16, wo16, nullptr, out, NQD, HID);
}

// round 17
// speedup vs baseline: 1.6782x; 1.0786x over previous
#include <cuda_runtime.h>
#include <cuda_fp16.h>
#include <math.h>
#include <stdint.h>

// ---------------- problem constants ----------------
#define S_LEN 2048
#define HID   3584
#define NH    28
#define NKV   4
#define HD    128
#define NQD   (NH*HD)    // 3584
#define NKD   (NKV*HD)   // 512
#define GRP   (NH/NKV)   // 7
#define NQKV  (NQD + 2*NKD)  // 4608

// ---------------- scratch (device globals; no allocs allowed) ----------------
__device__ float g_qkv[(size_t)S_LEN * NQKV];
__device__ float g_bias[NQKV];

__device__ __align__(16) __half g_hs16[S_LEN * HID];
__device__ __align__(16) __half g_ctx16[S_LEN * NQD];
__device__ __align__(16) __half g_q16h[S_LEN * NQD], g_q16l[S_LEN * NQD];
__device__ __align__(16) __half g_k16[S_LEN * NKD];
__device__ __align__(16) __half g_v16[S_LEN * NKD];
__device__ __align__(16) __half g_w16[(size_t)NQKV * HID];
__device__ __align__(16) __half g_wo16[(size_t)HID * NQD];

// ---------------- helpers ----------------
__device__ __forceinline__ uint32_t smem_u32(const void* p) {
    uint32_t a;
    asm("{ .reg .u64 t; cvta.to.shared.u64 t, %1; cvt.u32.u64 %0, t; }" : "=r"(a) : "l"(p));
    return a;
}

__device__ __forceinline__ void cp_async16(uint32_t dst, const void* src) {
    asm volatile("cp.async.cg.shared.global [%0], [%1], 16;" :: "r"(dst), "l"(src) : "memory");
}

__device__ __forceinline__ void ldm_x4(uint32_t* r, uint32_t addr) {
    asm volatile("ldmatrix.sync.aligned.m8n8.x4.shared.b16 {%0,%1,%2,%3}, [%4];"
                 : "=r"(r[0]), "=r"(r[1]), "=r"(r[2]), "=r"(r[3]) : "r"(addr));
}

__device__ __forceinline__ void ldm_x4_t(uint32_t* r, uint32_t addr) {
    asm volatile("ldmatrix.sync.aligned.m8n8.x4.trans.shared.b16 {%0,%1,%2,%3}, [%4];"
                 : "=r"(r[0]), "=r"(r[1]), "=r"(r[2]), "=r"(r[3]) : "r"(addr));
}

__device__ __forceinline__ void mma_f16(float* c, const uint32_t* a, const uint32_t* b) {
    asm volatile(
        "mma.sync.aligned.m16n8k16.row.col.f32.f16.f16.f32 "
        "{%0,%1,%2,%3}, {%4,%5,%6,%7}, {%8,%9}, {%0,%1,%2,%3};"
        : "+f"(c[0]), "+f"(c[1]), "+f"(c[2]), "+f"(c[3])
        : "r"(a[0]), "r"(a[1]), "r"(a[2]), "r"(a[3]), "r"(b[0]), "r"(b[1]));
}

__device__ __forceinline__ uint32_t pack_h2(float a, float b) {
    __half2 h = __floats2half2_rn(a, b);
    return *(uint32_t*)&h;
}

__device__ __forceinline__ float fexp2(float x) {
    float r;
    asm("ex2.approx.f32 %0, %1;" : "=f"(r) : "f"(x));
    return r;
}

// ---------------- convert kernels ----------------
__global__ void conv_h_kernel(const float4* __restrict__ X, __half2* __restrict__ H, int n4) {
    int i = blockIdx.x * 256 + threadIdx.x;
    if (i >= n4) return;
    float4 x = X[i];
    H[2*i]   = __floats2half2_rn(x.x, x.y);
    H[2*i+1] = __floats2half2_rn(x.z, x.w);
}

// merged QKV weight transpose + bias concat.
// grid.x: 0-111 -> Wq, 112-127 -> Wk, 128-143 -> Wv. blockIdx.y==0 rows also copy bias.
__global__ void tsplit_qkv_kernel(const float* __restrict__ Wq, const float* __restrict__ Wk,
                                  const float* __restrict__ Wv, __half* __restrict__ T,
                                  const float* __restrict__ bq, const float* __restrict__ bk,
                                  const float* __restrict__ bv, float* __restrict__ bias) {
    __shared__ float t[64][33];
    int bx = blockIdx.x;
    const float* W; const float* bsrc; int N; int n0; size_t tb; int boff;
    if (bx < 112)      { W = Wq; bsrc = bq; N = NQD; n0 = bx * 32;         tb = 0;                          boff = 0; }
    else if (bx < 128) { W = Wk; bsrc = bk; N = NKD; n0 = (bx - 112) * 32; tb = (size_t)NQD * HID;          boff = NQD; }
    else               { W = Wv; bsrc = bv; N = NKD; n0 = (bx - 128) * 32; tb = (size_t)(NQD + NKD) * HID;  boff = NQD + NKD; }
    int k0 = blockIdx.y * 64;
    int tx = threadIdx.x, ty = threadIdx.y;
    if (blockIdx.y == 0 && ty == 0) bias[boff + n0 + tx] = bsrc[n0 + tx];
#pragma unroll
    for (int i = 0; i < 8; i++) {
        int k = i * 8 + ty;
        t[k][tx] = W[(size_t)(k0 + k) * N + n0 + tx];
    }
    __syncthreads();
#pragma unroll
    for (int i = 0; i < 4; i++) {
        int n = i * 8 + ty;
        __half2 hp = __floats2half2_rn(t[2 * tx][n], t[2 * tx + 1][n]);
        *(__half2*)(T + tb + (size_t)(n0 + n) * HID + k0 + 2 * tx) = hp;
    }
}

// W [K,N] fp32 row-major -> T [N,K] fp16 (single). Tile 32n x 64k, block (32,8).
__global__ void tsplit2h_kernel(const float* __restrict__ W, __half* __restrict__ T,
                                int K, int N) {
    __shared__ float t[64][33];
    int n0 = blockIdx.x * 32, k0 = blockIdx.y * 64;
    int tx = threadIdx.x, ty = threadIdx.y;
#pragma unroll
    for (int i = 0; i < 8; i++) {
        int k = i * 8 + ty;
        t[k][tx] = W[(size_t)(k0 + k) * N + n0 + tx];
    }
    __syncthreads();
#pragma unroll
    for (int i = 0; i < 4; i++) {
        int n = i * 8 + ty;
        __half2 hp = __floats2half2_rn(t[2 * tx][n], t[2 * tx + 1][n]);
        *(__half2*)(T + (size_t)(n0 + n) * K + k0 + 2 * tx) = hp;
    }
}

// ---------------- mma.sync GEMM (fp16 1-term: A x B), BK=64, 2-stage, 1 sync/iter ----------------
#define GBK 64
#define ROWP 72
#define STG_TILE (128*ROWP*2)          // 18432 B per operand tile
#define STG1_BYTES (2*STG_TILE)        // 36864 B per stage (A, B)
#define GEMM1_SMEM (2*STG1_BYTES)      // 73728 B (2 stages)

__global__ __launch_bounds__(256, 2)
void gemm_f16_1t(const __half* __restrict__ A, const __half* __restrict__ B,
                 const float* __restrict__ bias,
                 float* __restrict__ C, int K, int Ntot) {
    extern __shared__ char smem[];
    const uint32_t sb = smem_u32(smem);
    const int tid = threadIdx.x;
    const int lane = tid & 31;
    const int warp = tid >> 5;
    const int wm = (warp >> 2) * 64;
    const int wn = (warp & 3) * 32;
    const int row0 = blockIdx.y * 128;
    const int col0 = blockIdx.x * 128;
    const int NI = K / GBK;

    float acc[4][4][4];
#pragma unroll
    for (int mt = 0; mt < 4; mt++)
#pragma unroll
        for (int nt = 0; nt < 4; nt++)
#pragma unroll
            for (int i = 0; i < 4; i++) acc[mt][nt][i] = 0.f;

    auto issue_load = [&](int stage, int kb) {
        uint32_t sbase = sb + stage * STG1_BYTES;
#pragma unroll
        for (int tile = 0; tile < 2; tile++) {
            const __half* src = (tile == 0) ? A : B;
            int gbase = (tile == 0) ? row0 : col0;
#pragma unroll
            for (int j = 0; j < 4; j++) {
                int s = j * 256 + tid;          // 0..1023
                int row = s >> 3;               // 0..127
                int c = (s & 7) << 3;           // 0..56 step 8 (halves)
                const void* g = src + (size_t)(gbase + row) * K + kb + c;
                uint32_t dst = sbase + tile * STG_TILE + (row * ROWP + c) * 2;
                cp_async16(dst, g);
            }
        }
        asm volatile("cp.async.commit_group;" ::: "memory");
    };

    issue_load(0, 0);

    for (int i = 0; i < NI; i++) {
        asm volatile("cp.async.wait_group 0;" ::: "memory");   // stage i landed
        __syncthreads();   // stage visible; compute(i-1) done block-wide
        if (i + 1 < NI) issue_load((i + 1) & 1, (i + 1) * GBK);

        const uint32_t sa = sb + (i & 1) * STG1_BYTES;
#pragma unroll
        for (int ks = 0; ks < 4; ks++) {
            uint32_t bh[4][2];
#pragma unroll
            for (int np = 0; np < 2; np++) {
                uint32_t addr = sa + STG_TILE +
                    ((wn + np * 16 + ((lane >> 4) << 3) + (lane & 7)) * ROWP
                     + ks * 16 + (((lane >> 3) & 1) << 3)) * 2;
                ldm_x4(&bh[np * 2][0], addr);
            }
#pragma unroll
            for (int mt = 0; mt < 4; mt++) {
                uint32_t ah[4];
                uint32_t addr = sa +
                    ((wm + mt * 16 + (lane & 15)) * ROWP + ks * 16 + ((lane >> 4) << 3)) * 2;
                ldm_x4(ah, addr);
#pragma unroll
                for (int nt = 0; nt < 4; nt++) {
                    mma_f16(acc[mt][nt], ah, bh[nt]);
                }
            }
        }
    }

#pragma unroll
    for (int mt = 0; mt < 4; mt++) {
#pragma unroll
        for (int nt = 0; nt < 4; nt++) {
            int r = row0 + wm + mt * 16 + (lane >> 2);
            int cidx = col0 + wn + nt * 8 + ((lane & 3) << 1);
            float b0 = 0.f, b1 = 0.f;
            if (bias) { b0 = bias[cidx]; b1 = bias[cidx + 1]; }
            float2* p0 = (float2*)(C + (size_t)r * Ntot + cidx);
            float2* p1 = (float2*)(C + (size_t)(r + 8) * Ntot + cidx);
            *p0 = make_float2(acc[mt][nt][0] + b0, acc[mt][nt][1] + b1);
            *p1 = make_float2(acc[mt][nt][2] + b0, acc[mt][nt][3] + b1);
        }
    }
}

// ---------------- fused mROPE + fp16 split ----------------
// q -> fp16 hi/lo (scaled by 1/sqrt(HD) * log2(e)), k -> fp16 single, v -> fp16 single
__global__ __launch_bounds__(256)
void rope_split_kernel(const float* __restrict__ qkv,
                       const float* __restrict__ cosp, const float* __restrict__ sinp,
                       __half* __restrict__ qh, __half* __restrict__ ql,
                       __half* __restrict__ k16, __half* __restrict__ v16) {
    const int s = blockIdx.x;
    const int lane = threadIdx.x & 31;
    const int grp = threadIdx.x >> 5;     // 0..7
    const int da = 2 * lane;              // even, 0..62
    const int sec = (da < 16) ? 0 : ((da < 40) ? 1 : 2);
    const int SH = S_LEN * HD;
    const float scale = 0.08838834764831845f * 1.4426950408889634f;

    const float2 c1 = *(const float2*)(cosp + sec * SH + s * HD + da);
    const float2 s1 = *(const float2*)(sinp + sec * SH + s * HD + da);
    const float2 c2 = *(const float2*)(cosp + sec * SH + s * HD + da + 64);
    const float2 s2 = *(const float2*)(sinp + sec * SH + s * HD + da + 64);

    const float* row = qkv + (size_t)s * NQKV;

    auto store2h = [](__half* H, __half* L, size_t o, float a, float b) {
        __half ha = __float2half_rn(a), hb = __float2half_rn(b);
        *(__half2*)(H + o) = __halves2half2(ha, hb);
        *(__half2*)(L + o) = __floats2half2_rn(a - __half2float(ha), b - __half2float(hb));
    };

#pragma unroll 1
    for (int it = 0; it < 5; it++) {
        int hh = it * 8 + grp;
        if (hh >= NH + 2 * NKV) break;
        if (hh < NH) {
            const float* base = row + hh * HD;
            float2 x1 = *(const float2*)(base + da);
            float2 x2 = *(const float2*)(base + da + 64);
            size_t o = (size_t)s * NQD + hh * HD;
            store2h(qh, ql, o + da,      (x1.x * c1.x - x2.x * s1.x) * scale,
                                         (x1.y * c1.y - x2.y * s1.y) * scale);
            store2h(qh, ql, o + da + 64, (x2.x * c2.x + x1.x * s2.x) * scale,
                                         (x2.y * c2.y + x1.y * s2.y) * scale);
        } else if (hh < NH + NKV) {
            int kvi = hh - NH;
            const float* base = row + NQD + kvi * HD;
            float2 x1 = *(const float2*)(base + da);
            float2 x2 = *(const float2*)(base + da + 64);
            size_t o = (size_t)s * NKD + kvi * HD;
            *(__half2*)(k16 + o + da)      = __floats2half2_rn(x1.x * c1.x - x2.x * s1.x,
                                                               x1.y * c1.y - x2.y * s1.y);
            *(__half2*)(k16 + o + da + 64) = __floats2half2_rn(x2.x * c2.x + x1.x * s2.x,
                                                               x2.y * c2.y + x1.y * s2.y);
        } else {
            int kvi = hh - NH - NKV;
            const float* base = row + NQD + NKD + kvi * HD;
            float2 x1 = *(const float2*)(base + da);
            float2 x2 = *(const float2*)(base + da + 64);
            size_t o = (size_t)s * NKD + kvi * HD;
            *(__half2*)(v16 + o + da)      = __floats2half2_rn(x1.x, x1.y);
            *(__half2*)(v16 + o + da + 64) = __floats2half2_rn(x2.x, x2.y);
        }
    }
}

// ---------------- attention: fp16 mma flash, BN=64, QK 2-term / PV 1-term ----------------
#define ATP 136
#define AT_ROWB (ATP*2)              // 272 B/row
#define AQ_TILE (128*AT_ROWB)        // 34816
#define KV_TILE (64*AT_ROWB)         // 17408
#define KV_STG  (2*KV_TILE)          // 34816 (K, V)
#define AQ_H 0
#define AQ_L AQ_TILE
#define AKV  (2*AQ_TILE)
#define ATTN_SMEM (AKV + 2*KV_STG)   // 139264 B

__global__ __launch_bounds__(256)
void attn_mma(const __half* __restrict__ qh, const __half* __restrict__ ql,
              const __half* __restrict__ k16, const __half* __restrict__ v16,
              __half* __restrict__ ctx16) {
    extern __shared__ char smem[];
    const uint32_t sb = smem_u32(smem);
    const int tid = threadIdx.x;
    const int lane = tid & 31;
    const int warp = tid >> 5;           // 0..7
    const int h = blockIdx.y;
    const int kvh = h / GRP;
    const int r0 = blockIdx.x * 128;

#pragma unroll
    for (int j = 0; j < 8; j++) {
        int idx = j * 256 + tid;
        int row = idx >> 4, c = idx & 15;
        size_t g = (size_t)(r0 + row) * NQD + h * HD + c * 8;
        uint32_t so = row * AT_ROWB + c * 16;
        cp_async16(sb + AQ_H + so, qh + g);
        cp_async16(sb + AQ_L + so, ql + g);
    }
    asm volatile("cp.async.commit_group;" ::: "memory");

    auto issue_kv = [&](int stage, int kt) {
        uint32_t base = sb + AKV + stage * KV_STG;
#pragma unroll
        for (int j = 0; j < 4; j++) {
            int idx = j * 256 + tid;
            int row = idx >> 4, c = idx & 15;
            size_t g = (size_t)(kt + row) * NKD + kvh * HD + c * 8;
            uint32_t so = row * AT_ROWB + c * 16;
            cp_async16(base + 0 * KV_TILE + so, k16 + g);
            cp_async16(base + 1 * KV_TILE + so, v16 + g);
        }
        asm volatile("cp.async.commit_group;" ::: "memory");
    };

    issue_kv(0, 0);
    asm volatile("cp.async.wait_group 1;" ::: "memory");
    __syncthreads();

    uint32_t qfh[8][4], qfl[8][4];
#pragma unroll
    for (int kf = 0; kf < 8; kf++) {
        uint32_t off = ((warp * 16 + (lane & 15)) * ATP + kf * 16 + ((lane >> 4) << 3)) * 2;
        ldm_x4(qfh[kf], sb + AQ_H + off);
        ldm_x4(qfl[kf], sb + AQ_L + off);
    }

    float o[16][4];
#pragma unroll
    for (int nt = 0; nt < 16; nt++)
#pragma unroll
        for (int i = 0; i < 4; i++) o[nt][i] = 0.f;
    float m0 = -INFINITY, m1 = -INFINITY, l0 = 0.f, l1 = 0.f;

    const int NI = S_LEN / 64;            // 32

    for (int it = 0; it < NI; it++) {
        asm volatile("cp.async.wait_group 0;" ::: "memory");
        __syncthreads();
        if (it + 1 < NI) issue_kv((it + 1) & 1, (it + 1) * 64);

        const uint32_t sk = sb + AKV + (it & 1) * KV_STG;

        float s[8][4];
#pragma unroll
        for (int nt = 0; nt < 8; nt++)
#pragma unroll
            for (int i = 0; i < 4; i++) s[nt][i] = 0.f;

#pragma unroll
        for (int kf = 0; kf < 8; kf++) {
            uint32_t kb[8][2];
#pragma unroll
            for (int np = 0; np < 4; np++) {
                uint32_t addr = sk +
                    ((np * 16 + ((lane >> 4) << 3) + (lane & 7)) * ATP
                     + kf * 16 + (((lane >> 3) & 1) << 3)) * 2;
                ldm_x4(&kb[np * 2][0], addr);
            }
#pragma unroll
            for (int nt = 0; nt < 8; nt++) {
                mma_f16(s[nt], qfh[kf], kb[nt]);
                mma_f16(s[nt], qfl[kf], kb[nt]);
            }
        }

        float mx0 = -INFINITY, mx1 = -INFINITY;
#pragma unroll
        for (int nt = 0; nt < 8; nt++) {
            mx0 = fmaxf(mx0, fmaxf(s[nt][0], s[nt][1]));
            mx1 = fmaxf(mx1, fmaxf(s[nt][2], s[nt][3]));
        }
        mx0 = fmaxf(mx0, __shfl_xor_sync(0xffffffffu, mx0, 1));
        mx0 = fmaxf(mx0, __shfl_xor_sync(0xffffffffu, mx0, 2));
        mx1 = fmaxf(mx1, __shfl_xor_sync(0xffffffffu, mx1, 1));
        mx1 = fmaxf(mx1, __shfl_xor_sync(0xffffffffu, mx1, 2));

        float nm0 = fmaxf(m0, mx0), nm1 = fmaxf(m1, mx1);
        float c0 = fexp2(m0 - nm0), c1 = fexp2(m1 - nm1);
        m0 = nm0; m1 = nm1;

        float sum0 = 0.f, sum1 = 0.f;
#pragma unroll
        for (int nt = 0; nt < 8; nt++) {
            s[nt][0] = fexp2(s[nt][0] - nm0);
            s[nt][1] = fexp2(s[nt][1] - nm0);
            s[nt][2] = fexp2(s[nt][2] - nm1);
            s[nt][3] = fexp2(s[nt][3] - nm1);
            sum0 += s[nt][0] + s[nt][1];
            sum1 += s[nt][2] + s[nt][3];
        }
        sum0 += __shfl_xor_sync(0xffffffffu, sum0, 1);
        sum0 += __shfl_xor_sync(0xffffffffu, sum0, 2);
        sum1 += __shfl_xor_sync(0xffffffffu, sum1, 1);
        sum1 += __shfl_xor_sync(0xffffffffu, sum1, 2);
        l0 = l0 * c0 + sum0;
        l1 = l1 * c1 + sum1;

#pragma unroll
        for (int nt = 0; nt < 16; nt++) {
            o[nt][0] *= c0; o[nt][1] *= c0;
            o[nt][2] *= c1; o[nt][3] *= c1;
        }

#pragma unroll
        for (int kf = 0; kf < 4; kf++) {
            uint32_t ah[4];
#pragma unroll
            for (int half = 0; half < 2; half++) {
                int nt = 2 * kf + half;
                ah[2 * half]     = pack_h2(s[nt][0], s[nt][1]);
                ah[2 * half + 1] = pack_h2(s[nt][2], s[nt][3]);
            }
#pragma unroll
            for (int np = 0; np < 8; np++) {
                uint32_t vb[4];
                uint32_t addr = sk + KV_TILE +
                    ((kf * 16 + (lane & 15)) * ATP + np * 16 + ((lane >> 4) << 3)) * 2;
                ldm_x4_t(vb, addr);
                mma_f16(o[2 * np],     ah, &vb[0]);
                mma_f16(o[2 * np + 1], ah, &vb[2]);
            }
        }
    }

    float inv0 = 1.f / l0, inv1 = 1.f / l1;
    int r_lo = r0 + warp * 16 + (lane >> 2);
    int r_hi = r_lo + 8;
#pragma unroll
    for (int nt = 0; nt < 16; nt++) {
        int col = h * HD + nt * 8 + ((lane & 3) << 1);
        *(__half2*)(ctx16 + (size_t)r_lo * NQD + col) =
            __floats2half2_rn(o[nt][0] * inv0, o[nt][1] * inv0);
        *(__half2*)(ctx16 + (size_t)r_hi * NQD + col) =
            __floats2half2_rn(o[nt][2] * inv1, o[nt][3] * inv1);
    }
}

// ---------------- launch ----------------
extern "C" void kernel_launch(void* const* d_in, const int* in_sizes, int n_in,
                              void* d_out, int out_size) {
    const float* hs   = (const float*)d_in[0];
    const float* cosp = (const float*)d_in[1];
    const float* sinp = (const float*)d_in[2];
    const float* Wq   = (const float*)d_in[3];
    const float* bq   = (const float*)d_in[4];
    const float* Wk   = (const float*)d_in[5];
    const float* bk   = (const float*)d_in[6];
    const float* Wv   = (const float*)d_in[7];
    const float* bv   = (const float*)d_in[8];
    const float* Wo   = (const float*)d_in[9];
    float* out = (float*)d_out;

    float *qkv_p, *bias_p;
    cudaGetSymbolAddress((void**)&qkv_p,  g_qkv);
    cudaGetSymbolAddress((void**)&bias_p, g_bias);

    __half *hs16, *w16, *wo16, *ctx16, *q16h, *q16l, *k16, *v16;
    cudaGetSymbolAddress((void**)&hs16,  g_hs16);
    cudaGetSymbolAddress((void**)&ctx16, g_ctx16);
    cudaGetSymbolAddress((void**)&w16,   g_w16);  cudaGetSymbolAddress((void**)&wo16, g_wo16);
    cudaGetSymbolAddress((void**)&q16h,  g_q16h); cudaGetSymbolAddress((void**)&q16l, g_q16l);
    cudaGetSymbolAddress((void**)&k16,   g_k16);  cudaGetSymbolAddress((void**)&v16,  g_v16);

    cudaFuncSetAttribute(gemm_f16_1t, cudaFuncAttributeMaxDynamicSharedMemorySize, GEMM1_SMEM);
    cudaFuncSetAttribute(attn_mma,    cudaFuncAttributeMaxDynamicSharedMemorySize, ATTN_SMEM);

    // 1) input convert + weight transposes (bias folded into QKV transpose)
    {
        int n4 = S_LEN * HID / 4;
        conv_h_kernel<<<(n4 + 255) / 256, 256>>>((const float4*)hs, (__half2*)hs16, n4);
    }
    {
        dim3 blk(32, 8);
        tsplit_qkv_kernel<<<dim3(144, HID / 64), blk>>>(Wq, Wk, Wv, w16, bq, bk, bv, bias_p);
        tsplit2h_kernel<<<dim3(HID / 32, NQD / 64), blk>>>(Wo, wo16, NQD, HID);
    }

    // 2) fused QKV projection (fp16 1-term, BK=64)
    gemm_f16_1t<<<dim3(NQKV / 128, S_LEN / 128), 256, GEMM1_SMEM>>>(hs16, w16, bias_p, qkv_p, HID, NQKV);

    // 3) fused mROPE + fp16 split (q hi/lo scaled with log2e folded; k,v single)
    rope_split_kernel<<<S_LEN, 256>>>(qkv_p, cosp, sinp, q16h, q16l, k16, v16);

    // 4) attention -> ctx (single fp16)
    {
        dim3 grid(S_LEN / 128, NH);
        attn_mma<<<grid, 256, ATTN_SMEM>>>(q16h, q16l, k16, v16, ctx16);
    }

    // 5) output projection (fp16 1-term, BK=64)
    gemm_f16_1t<<<dim3(HID / 128, S_LEN / 128), 256, GEMM1_SMEM>>>(ctx16, wo16, nullptr, out, NQD, HID);
}